// round 7
// baseline (speedup 1.0000x reference)
#include <cuda_runtime.h>

#define NB 256   // batch
#define NH 2048  // hidden
#define NG 6144  // 3*H
#define NT 512   // time steps
#define NO 14    // output classes

#define NBLK 384 // persistent blocks = GEMM tiles (4 x 96)
#define NTHR 128

// ---- device-global scratch (no allocations allowed) ----
__device__ float g_gh[NB * NG];            // gh scratch, 6 MB
__device__ float g_h[2 * NB * NH];         // ping-pong hidden state, 4 MB
__device__ int   g_topi[NB];
__device__ int   g_sel[NB];                // topi if alive else -1
__device__ unsigned g_bar_count;
__device__ unsigned g_bar_gen;

// =====================================================================
// Software grid barrier (all NBLK blocks are guaranteed co-resident)
// =====================================================================
__device__ __forceinline__ void grid_bar()
{
    __syncthreads();
    if (threadIdx.x == 0) {
        __threadfence();
        unsigned gen = *(volatile unsigned*)&g_bar_gen;
        unsigned arr = atomicAdd(&g_bar_count, 1u);
        if (arr == NBLK - 1) {
            *(volatile unsigned*)&g_bar_count = 0u;
            __threadfence();
            *(volatile unsigned*)&g_bar_gen = gen + 1u;
        } else {
            while (*(volatile unsigned*)&g_bar_gen == gen) { __nanosleep(64); }
        }
        __threadfence();
    }
    __syncthreads();
}

// =====================================================================
// One persistent kernel for the full 512-step decode
// =====================================================================
__global__ __launch_bounds__(NTHR, 3)
void decoder_kernel(const float* __restrict__ enc_h,
                    const float* __restrict__ target,
                    const float* __restrict__ W_ih,
                    const float* __restrict__ W_hh,
                    const float* __restrict__ b_ih,
                    const float* __restrict__ b_hh,
                    const float* __restrict__ W_out,
                    const float* __restrict__ b_out,
                    float* __restrict__ out)
{
    __shared__ float As[16][64];
    __shared__ float Bs[16][64];
    __shared__ float part[NO][NTHR];

    const int tid  = threadIdx.x;
    const int blk  = blockIdx.x;
    const int m0   = (blk / 96) * 64;        // GEMM tile origin (M)
    const int n0   = (blk % 96) * 64;        // GEMM tile origin (N)
    const int tn   = (tid & 7) * 8;          // 8 N-values per thread
    const int tm   = (tid >> 3) * 4;         // 4 M-values per thread
    const int gtid = blk * NTHR + tid;       // global thread id (49152)

    for (int t = 0; t < NT; t++) {
        const int par = t & 1;
        const float* hprev = (t == 0) ? enc_h : (g_h + (size_t)(1 - par) * NB * NH);

        // ---------------- phase 1: scan(t-1) in block 0 + GEMM ----------
        if (t > 0 && blk == 0 && tid < 32) {
            // warp-wide prefix-OR over 256 batch rows, 8 rows per lane
            int   tp[8];
            int   hit[8];
            unsigned chunk = 0;
#pragma unroll
            for (int i = 0; i < 8; i++) {
                tp[i]  = g_topi[tid * 8 + i];
                hit[i] = (tp[i] == NO - 1);
                chunk |= (unsigned)hit[i];
            }
            unsigned inc = chunk;
#pragma unroll
            for (int off = 1; off < 32; off <<= 1) {
                unsigned v = __shfl_up_sync(0xffffffffu, inc, off);
                if (tid >= off) inc |= v;
            }
            unsigned excl = __shfl_up_sync(0xffffffffu, inc, 1);
            unsigned run  = (tid == 0) ? 0u : excl;
#pragma unroll
            for (int i = 0; i < 8; i++) {
                int alive = !(run | (unsigned)hit[i]);
                g_sel[tid * 8 + i] = alive ? tp[i] : -1;
                run |= (unsigned)hit[i];
            }
        }

        // GEMM: g_gh[m][n] = sum_k hprev[m][k] * W_hh[n][k]
        {
            float acc[4][8];
#pragma unroll
            for (int i = 0; i < 4; i++)
#pragma unroll
                for (int j = 0; j < 8; j++) acc[i][j] = 0.f;

            const float* Ablk = hprev + (size_t)m0 * NH;
            const float* Wblk = W_hh  + (size_t)n0 * NH;

            for (int k0 = 0; k0 < NH; k0 += 16) {
#pragma unroll
                for (int l = 0; l < 2; l++) {
                    int j   = tid + l * NTHR;
                    int row = j >> 2;
                    int kq  = (j & 3) << 2;
                    float4 v = *(const float4*)(Ablk + (size_t)row * NH + k0 + kq);
                    As[kq + 0][row] = v.x; As[kq + 1][row] = v.y;
                    As[kq + 2][row] = v.z; As[kq + 3][row] = v.w;
                    float4 w = *(const float4*)(Wblk + (size_t)row * NH + k0 + kq);
                    Bs[kq + 0][row] = w.x; Bs[kq + 1][row] = w.y;
                    Bs[kq + 2][row] = w.z; Bs[kq + 3][row] = w.w;
                }
                __syncthreads();

#pragma unroll
                for (int kk = 0; kk < 16; kk++) {
                    float4 a  = *(const float4*)&As[kk][tm];
                    float4 b0 = *(const float4*)&Bs[kk][tn];
                    float4 b1 = *(const float4*)&Bs[kk][tn + 4];
                    float av[4] = {a.x, a.y, a.z, a.w};
                    float bv[8] = {b0.x, b0.y, b0.z, b0.w, b1.x, b1.y, b1.z, b1.w};
#pragma unroll
                    for (int i = 0; i < 4; i++)
#pragma unroll
                        for (int j = 0; j < 8; j++)
                            acc[i][j] = fmaf(av[i], bv[j], acc[i][j]);
                }
                __syncthreads();
            }

#pragma unroll
            for (int i = 0; i < 4; i++) {
                float4 o0 = make_float4(acc[i][0], acc[i][1], acc[i][2], acc[i][3]);
                float4 o1 = make_float4(acc[i][4], acc[i][5], acc[i][6], acc[i][7]);
                float* dst = g_gh + (size_t)(m0 + tm + i) * NG + n0 + tn;
                *(float4*)dst       = o0;
                *(float4*)(dst + 4) = o1;
            }
        }
        grid_bar();

        // ---------------- phase 2: gate fusion --------------------------
        {
            float* hnew = g_h + (size_t)par * NB * NH;
            for (int idx = gtid; idx < NB * NH; idx += NBLK * NTHR) {
                const int b = idx >> 11;        // / NH
                const int j = idx & (NH - 1);   // % NH

                float ghr = g_gh[(size_t)b * NG + j]          + b_hh[j];
                float ghz = g_gh[(size_t)b * NG + NH + j]     + b_hh[NH + j];
                float ghn = g_gh[(size_t)b * NG + 2 * NH + j] + b_hh[2 * NH + j];
                float gir = b_ih[j], giz = b_ih[NH + j], gin = b_ih[2 * NH + j];

                if (t == 0) {
#pragma unroll
                    for (int o = 0; o < NO; o++) {
                        float xv = fmaxf(target[(size_t)b * NT * NO + o], 0.f);
                        gir = fmaf(xv, W_ih[(size_t)j * NO + o], gir);
                        giz = fmaf(xv, W_ih[(size_t)(NH + j) * NO + o], giz);
                        gin = fmaf(xv, W_ih[(size_t)(2 * NH + j) * NO + o], gin);
                    }
                } else {
                    int s = g_sel[b];
                    if (s >= 0) {
                        gir += W_ih[(size_t)j * NO + s];
                        giz += W_ih[(size_t)(NH + j) * NO + s];
                        gin += W_ih[(size_t)(2 * NH + j) * NO + s];
                    }
                }

                float r  = 1.f / (1.f + expf(-(gir + ghr)));
                float z  = 1.f / (1.f + expf(-(giz + ghz)));
                float n  = tanhf(gin + r * ghn);
                float hp = hprev[(size_t)b * NH + j];
                hnew[(size_t)b * NH + j] = (1.f - z) * n + z * hp;
            }
        }
        grid_bar();

        // ---------------- phase 3: logits + argmax + log_softmax --------
        if (blk < NB) {
            const int b = blk;
            const float* h = g_h + (size_t)par * NB * NH + (size_t)b * NH;

            float acc[NO];
#pragma unroll
            for (int o = 0; o < NO; o++) acc[o] = 0.f;

            for (int k = tid; k < NH; k += NTHR) {
                float hv = h[k];
#pragma unroll
                for (int o = 0; o < NO; o++)
                    acc[o] = fmaf(hv, W_out[(size_t)o * NH + k], acc[o]);
            }

#pragma unroll
            for (int o = 0; o < NO; o++) part[o][tid] = acc[o];
            __syncthreads();

            for (int s = 64; s > 0; s >>= 1) {
                if (tid < s) {
#pragma unroll
                    for (int o = 0; o < NO; o++) part[o][tid] += part[o][tid + s];
                }
                __syncthreads();
            }

            if (tid == 0) {
                float l[NO];
                float m = -1e30f;
#pragma unroll
                for (int o = 0; o < NO; o++) { l[o] = part[o][0] + b_out[o]; m = fmaxf(m, l[o]); }
                int   bi = 0;
                float bv = l[0];
#pragma unroll
                for (int o = 1; o < NO; o++)
                    if (l[o] > bv) { bv = l[o]; bi = o; }   // first-max, matches jnp.argmax
                float s = 0.f;
#pragma unroll
                for (int o = 0; o < NO; o++) s += expf(l[o] - m);
                float lse = m + logf(s);
                float* dst = out + ((size_t)b * NT + t) * NO;
#pragma unroll
                for (int o = 0; o < NO; o++) dst[o] = l[o] - lse;
                g_topi[b] = bi;
            }
            __syncthreads();
        }
        grid_bar();
    }

    // ---------------- tail: append h_final ------------------------------
    {
        const float* hf = g_h + (size_t)((NT - 1) & 1) * NB * NH;
        float* tail = out + (size_t)NB * NT * NO;
        for (int i = gtid; i < NB * NH / 4; i += NBLK * NTHR) {
            float4 v = *(const float4*)(hf + (size_t)i * 4);
            *(float4*)(tail + (size_t)i * 4) = v;
        }
    }
}

// =====================================================================
extern "C" void kernel_launch(void* const* d_in, const int* in_sizes, int n_in,
                              void* d_out, int out_size)
{
    // inputs: 0 encoder_outputs (unused), 1 encoder_hidden, 2 target_tensor,
    //         3 W_ih, 4 W_hh, 5 b_ih, 6 b_hh, 7 W_out, 8 b_out
    const float* enc_h  = (const float*)d_in[1];
    const float* target = (const float*)d_in[2];
    const float* W_ih   = (const float*)d_in[3];
    const float* W_hh   = (const float*)d_in[4];
    const float* b_ih   = (const float*)d_in[5];
    const float* b_hh   = (const float*)d_in[6];
    const float* W_out  = (const float*)d_in[7];
    const float* b_out  = (const float*)d_in[8];
    float* out = (float*)d_out;

    decoder_kernel<<<NBLK, NTHR>>>(enc_h, target, W_ih, W_hh, b_ih, b_hh,
                                   W_out, b_out, out);
}

// round 10
// speedup vs baseline: 1.5343x; 1.5343x over previous
#include <cuda_runtime.h>
#include <cstdint>

#define NB 256   // batch
#define NH 2048  // hidden
#define NG 6144  // 3*H
#define NT 512   // time steps
#define NO 14    // output classes

#define NBLK 96  // persistent blocks, each owns one 128x128 C tile (2 x 48)
#define NTHR 256 // 8 warps: 2x4 warp grid, each warp 64x32 of C
#define BK 32    // k per staged iteration
#define KITERS (NH / BK)
#define LDA 36   // smem row stride in floats (conflict-free: 36 == 4 mod 32)

// dynamic smem: A0 A1 B0 B1, each 128*36 floats
#define TILE_F (128 * LDA)
#define SMEM_DYN (4 * TILE_F * 4)

// ---- device-global scratch (no allocations allowed) ----
__device__ float g_gh[NB * NG];            // gh scratch [b][n], 6 MB
__device__ float g_h[2 * NB * NH];         // ping-pong hidden state, 4 MB
__device__ int   g_topi[NB];
__device__ int   g_sel[NB];
__device__ unsigned g_bar_count;
__device__ unsigned g_bar_gen;

// =====================================================================
// helpers
// =====================================================================
__device__ __forceinline__ uint32_t smem_u32(const void* p) {
    uint32_t a;
    asm("{ .reg .u64 t; cvta.to.shared.u64 t, %1; cvt.u32.u64 %0, t; }"
        : "=r"(a) : "l"(p));
    return a;
}

#define CP_ASYNC16(saddr, gptr) \
    asm volatile("cp.async.cg.shared.global [%0], [%1], 16;" \
                 :: "r"(saddr), "l"(gptr) : "memory")
#define CP_COMMIT()  asm volatile("cp.async.commit_group;" ::: "memory")
#define CP_WAIT(n)   asm volatile("cp.async.wait_group %0;" :: "n"(n) : "memory")

// tf32 split: v = hi + lo, both tf32-representable (round-to-nearest)
__device__ __forceinline__ void tf32_split(float v, uint32_t& hi, uint32_t& lo) {
    asm("cvt.rna.tf32.f32 %0, %1;" : "=r"(hi) : "f"(v));
    float rl = v - __uint_as_float(hi);
    asm("cvt.rna.tf32.f32 %0, %1;" : "=r"(lo) : "f"(rl));
}

// C += A(16x8,row) * B(8x8,col)   tf32 -> f32
#define MMA8(c, a0, a1, a2, a3, b0, b1) \
    asm volatile("mma.sync.aligned.m16n8k8.row.col.f32.tf32.tf32.f32 " \
        "{%0,%1,%2,%3},{%4,%5,%6,%7},{%8,%9},{%0,%1,%2,%3};" \
        : "+f"((c)[0]), "+f"((c)[1]), "+f"((c)[2]), "+f"((c)[3]) \
        : "r"(a0), "r"(a1), "r"(a2), "r"(a3), "r"(b0), "r"(b1))

// =====================================================================
// Software grid barrier (all NBLK blocks co-resident; 96 <= 148 SMs)
// =====================================================================
__device__ __forceinline__ void grid_bar()
{
    __syncthreads();
    if (threadIdx.x == 0) {
        __threadfence();
        unsigned gen = *(volatile unsigned*)&g_bar_gen;
        unsigned arr = atomicAdd(&g_bar_count, 1u);
        if (arr == NBLK - 1) {
            *(volatile unsigned*)&g_bar_count = 0u;
            __threadfence();
            *(volatile unsigned*)&g_bar_gen = gen + 1u;
        } else {
            while (*(volatile unsigned*)&g_bar_gen == gen) { __nanosleep(64); }
        }
        __threadfence();
    }
    __syncthreads();
}

// =====================================================================
// persistent kernel for the full 512-step decode (tf32 mma.sync GEMM)
// =====================================================================
__global__ __launch_bounds__(NTHR, 1)
void decoder_kernel(const float* __restrict__ enc_h,
                    const float* __restrict__ target,
                    const float* __restrict__ W_ih,
                    const float* __restrict__ W_hh,
                    const float* __restrict__ b_ih,
                    const float* __restrict__ b_hh,
                    const float* __restrict__ W_out,
                    const float* __restrict__ b_out,
                    float* __restrict__ out)
{
    extern __shared__ float smf[];   // [4][128*LDA] : A0 A1 B0 B1

    const int tid = threadIdx.x;
    const int w   = tid >> 5;        // warp 0..7
    const int lid = tid & 31;
    const int gid = lid >> 2;        // groupID 0..7
    const int tig = lid & 3;         // thread-in-group 0..3
    const int wm  = w >> 2;          // 0..1 : warp row (64 M each)
    const int wn  = w & 3;           // 0..3 : warp col (32 N each)
    const int blk  = blockIdx.x;
    const int m0   = (blk / 48) * 128;
    const int n0   = (blk % 48) * 128;
    const int gtid = blk * NTHR + tid;

    const uint32_t sb  = smem_u32(smf);
    const uint32_t sA[2] = { sb,                sb + TILE_F * 4 };
    const uint32_t sB[2] = { sb + 2 * TILE_F * 4, sb + 3 * TILE_F * 4 };

    for (int t = 0; t < NT; t++) {
        const int par = t & 1;
        const float* hprev = (t == 0) ? enc_h : (g_h + (size_t)(1 - par) * NB * NH);

        // ---------- scan(t-1): block 0, warp 0 (before GEMM loop) -------
        if (t > 0 && blk == 0 && w == 0) {
            int tp[8]; int hit[8]; unsigned chunk = 0;
#pragma unroll
            for (int i = 0; i < 8; i++) {
                tp[i]  = g_topi[lid * 8 + i];
                hit[i] = (tp[i] == NO - 1);
                chunk |= (unsigned)hit[i];
            }
            unsigned inc = chunk;
#pragma unroll
            for (int off = 1; off < 32; off <<= 1) {
                unsigned v = __shfl_up_sync(0xffffffffu, inc, off);
                if (lid >= off) inc |= v;
            }
            unsigned excl = __shfl_up_sync(0xffffffffu, inc, 1);
            unsigned run  = (lid == 0) ? 0u : excl;
#pragma unroll
            for (int i = 0; i < 8; i++) {
                int alive = !(run | (unsigned)hit[i]);
                g_sel[lid * 8 + i] = alive ? tp[i] : -1;
                run |= (unsigned)hit[i];
            }
        }

        // ---------- GEMM: g_gh[m][n] = hprev[m][:] . W_hh[n][:] --------
        {
            const float* Ag = hprev + (size_t)m0 * NH;
            const float* Bg = W_hh  + (size_t)n0 * NH;

            float acc[4][4][4];
#pragma unroll
            for (int i = 0; i < 4; i++)
#pragma unroll
                for (int j = 0; j < 4; j++)
#pragma unroll
                    for (int c = 0; c < 4; c++) acc[i][j][c] = 0.f;

            // prefetch iter 0
            {
#pragma unroll
                for (int i = 0; i < 4; i++) {
                    int idx = tid + i * NTHR;
                    int row = idx >> 3;
                    int c4  = (idx & 7) << 2;
                    uint32_t off = (uint32_t)(row * LDA + c4) * 4u;
                    CP_ASYNC16(sA[0] + off, Ag + (size_t)row * NH + c4);
                    CP_ASYNC16(sB[0] + off, Bg + (size_t)row * NH + c4);
                }
                CP_COMMIT();
            }

            for (int it = 0; it < KITERS; it++) {
                const int p = it & 1;
                if (it + 1 < KITERS) {
                    const int k0 = (it + 1) * BK;
#pragma unroll
                    for (int i = 0; i < 4; i++) {
                        int idx = tid + i * NTHR;
                        int row = idx >> 3;
                        int c4  = (idx & 7) << 2;
                        uint32_t off = (uint32_t)(row * LDA + c4) * 4u;
                        CP_ASYNC16(sA[p ^ 1] + off, Ag + (size_t)row * NH + k0 + c4);
                        CP_ASYNC16(sB[p ^ 1] + off, Bg + (size_t)row * NH + k0 + c4);
                    }
                    CP_COMMIT();
                    CP_WAIT(1);
                } else {
                    CP_WAIT(0);
                }
                __syncthreads();

                const float* As = smf + p * TILE_F;
                const float* Bs = smf + (2 + p) * TILE_F;

#pragma unroll
                for (int ks = 0; ks < 4; ks++) {
                    const int kc = ks * 8 + tig;

                    uint32_t bh[4][2], bl[4][2];
#pragma unroll
                    for (int nf = 0; nf < 4; nf++) {
                        const float* bp = Bs + (wn * 32 + nf * 8 + gid) * LDA + kc;
                        tf32_split(bp[0], bh[nf][0], bl[nf][0]);
                        tf32_split(bp[4], bh[nf][1], bl[nf][1]);
                    }
#pragma unroll
                    for (int mf = 0; mf < 4; mf++) {
                        const float* ap = As + (wm * 64 + mf * 16 + gid) * LDA + kc;
                        uint32_t ah[4], al[4];
                        tf32_split(ap[0],           ah[0], al[0]);
                        tf32_split(ap[8 * LDA],     ah[1], al[1]);
                        tf32_split(ap[4],           ah[2], al[2]);
                        tf32_split(ap[8 * LDA + 4], ah[3], al[3]);
#pragma unroll
                        for (int nf = 0; nf < 4; nf++) {
                            MMA8(acc[mf][nf], al[0], al[1], al[2], al[3],
                                 bh[nf][0], bh[nf][1]);
                            MMA8(acc[mf][nf], ah[0], ah[1], ah[2], ah[3],
                                 bl[nf][0], bl[nf][1]);
                            MMA8(acc[mf][nf], ah[0], ah[1], ah[2], ah[3],
                                 bh[nf][0], bh[nf][1]);
                        }
                    }
                }
                __syncthreads();
            }

            // epilogue: registers -> g_gh (float2 stores)
#pragma unroll
            for (int mf = 0; mf < 4; mf++) {
                const int row = m0 + wm * 64 + mf * 16 + gid;
#pragma unroll
                for (int nf = 0; nf < 4; nf++) {
                    const int col = n0 + wn * 32 + nf * 8 + 2 * tig;
                    float2 v0 = make_float2(acc[mf][nf][0], acc[mf][nf][1]);
                    float2 v1 = make_float2(acc[mf][nf][2], acc[mf][nf][3]);
                    *(float2*)(g_gh + (size_t)row * NG + col)       = v0;
                    *(float2*)(g_gh + (size_t)(row + 8) * NG + col) = v1;
                }
            }
        }
        grid_bar();

        // ---------------- gate fusion ----------------------------------
        {
            float* hnew = g_h + (size_t)par * NB * NH;
            for (int idx = gtid; idx < NB * NH; idx += NBLK * NTHR) {
                const int b = idx >> 11;        // / NH
                const int j = idx & (NH - 1);   // % NH

                float ghr = g_gh[(size_t)b * NG + j]          + b_hh[j];
                float ghz = g_gh[(size_t)b * NG + NH + j]     + b_hh[NH + j];
                float ghn = g_gh[(size_t)b * NG + 2 * NH + j] + b_hh[2 * NH + j];
                float gir = b_ih[j], giz = b_ih[NH + j], gin = b_ih[2 * NH + j];

                if (t == 0) {
#pragma unroll
                    for (int o = 0; o < NO; o++) {
                        float xv = fmaxf(target[(size_t)b * NT * NO + o], 0.f);
                        gir = fmaf(xv, W_ih[(size_t)j * NO + o], gir);
                        giz = fmaf(xv, W_ih[(size_t)(NH + j) * NO + o], giz);
                        gin = fmaf(xv, W_ih[(size_t)(2 * NH + j) * NO + o], gin);
                    }
                } else {
                    int s = g_sel[b];
                    if (s >= 0) {
                        gir += W_ih[(size_t)j * NO + s];
                        giz += W_ih[(size_t)(NH + j) * NO + s];
                        gin += W_ih[(size_t)(2 * NH + j) * NO + s];
                    }
                }

                float r  = 1.f / (1.f + expf(-(gir + ghr)));
                float z  = 1.f / (1.f + expf(-(giz + ghz)));
                float n  = tanhf(gin + r * ghn);
                float hp = hprev[(size_t)b * NH + j];
                hnew[(size_t)b * NH + j] = (1.f - z) * n + z * hp;
            }
        }
        grid_bar();

        // ------- logits + argmax + log_softmax : one warp per row -------
        {
            const int gw = blk * 8 + w;   // 768 warps, rows 0..255 active
            if (gw < NB) {
                const float* h = g_h + (size_t)par * NB * NH + (size_t)gw * NH;

                float acc[NO];
#pragma unroll
                for (int o = 0; o < NO; o++) acc[o] = 0.f;

                for (int k = lid; k < NH; k += 32) {
                    float hv = h[k];
#pragma unroll
                    for (int o = 0; o < NO; o++)
                        acc[o] = fmaf(hv, W_out[(size_t)o * NH + k], acc[o]);
                }
#pragma unroll
                for (int o = 0; o < NO; o++) {
#pragma unroll
                    for (int off = 16; off > 0; off >>= 1)
                        acc[o] += __shfl_xor_sync(0xffffffffu, acc[o], off);
                }

                if (lid == 0) {
                    float l[NO];
                    float m = -1e30f;
#pragma unroll
                    for (int o = 0; o < NO; o++) { l[o] = acc[o] + b_out[o]; m = fmaxf(m, l[o]); }
                    int   bi = 0;
                    float bv = l[0];
#pragma unroll
                    for (int o = 1; o < NO; o++)
                        if (l[o] > bv) { bv = l[o]; bi = o; }   // first-max = jnp.argmax
                    float s = 0.f;
#pragma unroll
                    for (int o = 0; o < NO; o++) s += expf(l[o] - m);
                    float lse = m + logf(s);
                    float* dst = out + ((size_t)gw * NT + t) * NO;
#pragma unroll
                    for (int o = 0; o < NO; o++) dst[o] = l[o] - lse;
                    g_topi[gw] = bi;
                }
            }
        }
        grid_bar();
    }

    // ---------------- tail: append h_final ------------------------------
    {
        const float* hf = g_h + (size_t)((NT - 1) & 1) * NB * NH;
        float* tail = out + (size_t)NB * NT * NO;
        for (int i = gtid; i < NB * NH / 4; i += NBLK * NTHR) {
            float4 v = *(const float4*)(hf + (size_t)i * 4);
            *(float4*)(tail + (size_t)i * 4) = v;
        }
    }
}

// =====================================================================
extern "C" void kernel_launch(void* const* d_in, const int* in_sizes, int n_in,
                              void* d_out, int out_size)
{
    // inputs: 0 encoder_outputs (unused), 1 encoder_hidden, 2 target_tensor,
    //         3 W_ih, 4 W_hh, 5 b_ih, 6 b_hh, 7 W_out, 8 b_out
    const float* enc_h  = (const float*)d_in[1];
    const float* target = (const float*)d_in[2];
    const float* W_ih   = (const float*)d_in[3];
    const float* W_hh   = (const float*)d_in[4];
    const float* b_ih   = (const float*)d_in[5];
    const float* b_hh   = (const float*)d_in[6];
    const float* W_out  = (const float*)d_in[7];
    const float* b_out  = (const float*)d_in[8];
    float* out = (float*)d_out;

    cudaFuncSetAttribute(decoder_kernel,
                         cudaFuncAttributeMaxDynamicSharedMemorySize, SMEM_DYN);

    decoder_kernel<<<NBLK, NTHR, SMEM_DYN>>>(enc_h, target, W_ih, W_hh,
                                             b_ih, b_hh, W_out, b_out, out);
}